// round 13
// baseline (speedup 1.0000x reference)
#include <cuda_runtime.h>
#include <cuda_bf16.h>
#include <cstdint>

#define Nst 512
#define Cc  512
#define NN  ((long)Nst * Nst)
#define KS4 2048                         // 4-segment K' for K=512
#define UK4 512                          // 4-segment K' for K=128
#define SLOT4 ((long)Nst * KS4)
#define KC   64
#define LDA  72                          // KC + 8 bf16 pad

typedef __nv_bfloat16 bf16;

// ---------------- static scratch (no runtime allocation) ----------------
__device__ float g_pw[20][Nst * Nst];        // fp32 powers
__device__ bf16  g_pwA[20][Nst * KS4];       // A-form split [h|l|h|l], natural rows
__device__ bf16  g_pwB[20][Nst * KS4];       // B-form split [h|h|l|l], TRANSPOSED (squaring)
__device__ bf16  g_pwN[20][Nst * KS4];       // B-form split [h|h|l|l], natural rows (x@P^T)
__device__ float g_G[128 * Nst];             // G[m] = A^m b
__device__ bf16  g_GA[64 * KS4];             // A-form split of G rows
__device__ bf16  g_GrevB[Nst * UK4];         // B-form of reversed G (K=128)
__device__ bf16  g_UA[Cc * UK4];             // A-form of u chunks (K=128)
__device__ bf16  g_GmatB[(size_t)65536 * UK4];
__device__ float g_R0[Cc * Nst], g_R1[Cc * Nst];
__device__ bf16  g_R0e[Cc * KS4], g_R1e[Cc * KS4];
__device__ float g_OutA[(size_t)128 * Cc * Nst];   // [j][c][n]
__device__ bf16  g_OutAe[(size_t)64 * Cc * KS4];   // A-form of rows j=0..63

// ---------------- helpers ----------------
__device__ __forceinline__ uint32_t s2u(const void* p) {
    uint32_t a;
    asm("{ .reg .u64 t; cvta.to.shared.u64 t, %1; cvt.u32.u64 %0, t; }" : "=r"(a) : "l"(p));
    return a;
}
__device__ __forceinline__ void cpasync(uint32_t d, const void* g, int srcsz) {
    asm volatile("cp.async.ca.shared.global [%0], [%1], 16, %2;"
                 :: "r"(d), "l"(g), "r"(srcsz) : "memory");
}
__device__ __forceinline__ void cpcommit() {
    asm volatile("cp.async.commit_group;" ::: "memory");
}
template<int n> __device__ __forceinline__ void cpwait() {
    asm volatile("cp.async.wait_group %0;" :: "n"(n) : "memory");
}
__device__ __forceinline__ void ldsm4(uint32_t &r0, uint32_t &r1, uint32_t &r2, uint32_t &r3, uint32_t a) {
    asm volatile("ldmatrix.sync.aligned.m8n8.x4.shared.b16 {%0,%1,%2,%3}, [%4];"
                 : "=r"(r0), "=r"(r1), "=r"(r2), "=r"(r3) : "r"(a));
}
__device__ __forceinline__ void mma16816(float* c, const uint32_t* a, const uint32_t* b) {
    asm volatile("mma.sync.aligned.m16n8k16.row.col.f32.bf16.bf16.f32 "
                 "{%0,%1,%2,%3}, {%4,%5,%6,%7}, {%8,%9}, {%0,%1,%2,%3};"
                 : "+f"(c[0]), "+f"(c[1]), "+f"(c[2]), "+f"(c[3])
                 : "r"(a[0]), "r"(a[1]), "r"(a[2]), "r"(a[3]), "r"(b[0]), "r"(b[1]));
}

// ============================================================================
// bf16 tensor-core GEMM: C[m,g] = sum_k A[m,k]*B[g,k] (+Dadd), M-guarded.
// Template BM = 128 (warp 32x64) or 256 (warp 64x64); BN = 128; KC = 64.
// 3-stage cp.async pipeline, ONE __syncthreads per stage.
// Epilogue: fp32 C store (+dMode add), optional 4-seg split emissions
// SA ([h|l|h|l] rows, stride 2048) / SB ([h|h|l|l] transposed, stride 2048).
// ============================================================================
template<int BM>
__global__ void __launch_bounds__(256, 1)
tgemm_k(const bf16* __restrict__ A, long aBase, long aZS,
        const bf16* __restrict__ B, long bBase, long bZS,
        float* __restrict__ C, long cBase, long cRS, long cZS,
        const float* __restrict__ Dadd, long dBase, long dRS, int dMode,
        bf16* __restrict__ SA, long saBase, long saZS,
        bf16* __restrict__ SB, long sbBase, long sbZS,
        int M, int Ks)
{
    constexpr int MI = BM / 64;          // 2 or 4 (m16 fragments per warp)
    constexpr int ROWS = BM + 128;
    constexpr int STAGE = ROWS * LDA;
    extern __shared__ bf16 sm[];

    int tid = threadIdx.x;
    int lane = tid & 31, wid = tid >> 5;
    int bm = blockIdx.y * BM, bn = blockIdx.x << 7;
    int z = blockIdx.z;
    const bf16* Ap = A + aBase + (long)z * aZS;
    const bf16* Bp = B + bBase + (long)z * bZS;
    int wm = (wid & 3) * (BM / 4);
    int wn = (wid >> 2) << 6;

    float acc[MI][8][4];
#pragma unroll
    for (int i = 0; i < MI; i++)
#pragma unroll
        for (int j = 0; j < 8; j++)
#pragma unroll
            for (int p = 0; p < 4; p++) acc[i][j][p] = 0.f;

    int nc = Ks / KC;

    auto ldg = [&](int s) {
        bf16* st = sm + (s % 3) * STAGE;
        int kc = s * KC;
#pragma unroll
        for (int t = 0; t < ROWS / 32; t++) {
            int id = tid + t * 256;
            int r = id >> 3, c = (id & 7) << 3;
            const bf16* src;
            int sz = 16;
            if (r < BM) {
                int gr = bm + r;
                int grs = gr < M ? gr : 0;
                src = Ap + (long)grs * Ks + kc + c;
                sz = gr < M ? 16 : 0;
            } else {
                src = Bp + (long)(bn + r - BM) * Ks + kc + c;
            }
            cpasync(s2u(st + r * LDA + c), src, sz);
        }
    };

    auto comp = [&](int s) {
        const bf16* as = sm + (s % 3) * STAGE;
        const bf16* bs = as + BM * LDA;
        int lr = lane & 15, lk = (lane >> 4) << 3;
#pragma unroll
        for (int ks = 0; ks < KC / 16; ks++) {
            uint32_t af[MI][4], bfr[8][2];
#pragma unroll
            for (int mi = 0; mi < MI; mi++) {
                uint32_t a = s2u(as + (wm + mi * 16 + lr) * LDA + ks * 16 + lk);
                ldsm4(af[mi][0], af[mi][1], af[mi][2], af[mi][3], a);
            }
#pragma unroll
            for (int nj = 0; nj < 4; nj++) {
                uint32_t r0, r1, r2, r3;
                uint32_t a = s2u(bs + (wn + nj * 16 + lr) * LDA + ks * 16 + lk);
                ldsm4(r0, r1, r2, r3, a);
                bfr[nj * 2][0] = r0;     bfr[nj * 2][1] = r2;
                bfr[nj * 2 + 1][0] = r1; bfr[nj * 2 + 1][1] = r3;
            }
#pragma unroll
            for (int mi = 0; mi < MI; mi++)
#pragma unroll
                for (int ni = 0; ni < 8; ni++)
                    mma16816(acc[mi][ni], af[mi], bfr[ni]);
        }
    };

    // 3-stage pipeline, one sync per stage: loads for stage s+2 go into the
    // slot whose compute (s-1) finished before this iteration's barrier.
    ldg(0); cpcommit();
    if (nc > 1) { ldg(1); cpcommit(); }
    for (int s = 0; s < nc; s++) {
        if (s + 1 < nc) cpwait<1>(); else cpwait<0>();
        __syncthreads();
        comp(s);
        if (s + 2 < nc) { ldg(s + 2); cpcommit(); }
    }

    // ---- epilogue ----
    int group = lane >> 2, t4 = lane & 3;
#pragma unroll
    for (int mi = 0; mi < MI; mi++) {
#pragma unroll
        for (int rh = 0; rh < 2; rh++) {
            int m = bm + wm + mi * 16 + rh * 8 + group;
            if (m >= M) continue;
            long cro = cBase + (long)z * cZS + (long)m * cRS;
#pragma unroll
            for (int ni = 0; ni < 8; ni++) {
                int n = bn + wn + ni * 8 + t4 * 2;
                float v0 = acc[mi][ni][rh * 2 + 0];
                float v1 = acc[mi][ni][rh * 2 + 1];
                if (dMode == 1) {
                    const float* dp = Dadd + dBase + (long)m * dRS + n;
                    v0 += dp[0]; v1 += dp[1];
                } else if (dMode == 2) {
                    long db = ((long)(n >> 9) << 18) + ((long)m << 9) + (n & 511);
                    v0 += Dadd[db]; v1 += Dadd[db + 1];
                }
                float2 vv; vv.x = v0; vv.y = v1;
                *(float2*)&C[cro + n] = vv;
                if (SA) {
                    bf16 h0 = __float2bfloat16(v0);
                    bf16 l0 = __float2bfloat16(v0 - __bfloat162float(h0));
                    bf16 h1 = __float2bfloat16(v1);
                    bf16 l1 = __float2bfloat16(v1 - __bfloat162float(h1));
                    long so = saBase + (long)z * saZS + (long)m * KS4 + n;
                    SA[so] = h0;     SA[so + 512] = l0;
                    SA[so + 1024] = h0; SA[so + 1536] = l0;
                    SA[so + 1] = h1;    SA[so + 513] = l1;
                    SA[so + 1025] = h1; SA[so + 1537] = l1;
                }
                if (SB) {
                    bf16 h0 = __float2bfloat16(v0);
                    bf16 l0 = __float2bfloat16(v0 - __bfloat162float(h0));
                    bf16 h1 = __float2bfloat16(v1);
                    bf16 l1 = __float2bfloat16(v1 - __bfloat162float(h1));
                    long so0 = sbBase + (long)z * sbZS + (long)n * KS4 + m;
                    SB[so0] = h0; SB[so0 + 512] = h0;
                    SB[so0 + 1024] = l0; SB[so0 + 1536] = l0;
                    long so1 = so0 + KS4;
                    SB[so1] = h1; SB[so1 + 512] = h1;
                    SB[so1 + 1024] = l1; SB[so1 + 1536] = l1;
                }
            }
        }
    }
}

// ---------------- conversion kernels (4-segment) ----------------
__global__ void splitA_k(const float* __restrict__ src, int ld,
                         bf16* __restrict__ dst, int M, int K) {
    long idx = (long)blockIdx.x * 256 + threadIdx.x;
    if (idx >= (long)M * K) return;
    int mm = (int)(idx / K), k = (int)(idx - (long)mm * K);
    float v = src[(long)mm * ld + k];
    bf16 h = __float2bfloat16(v);
    bf16 l = __float2bfloat16(v - __bfloat162float(h));
    long o = (long)mm * 4 * K + k;
    dst[o] = h; dst[o + K] = l; dst[o + 2 * K] = h; dst[o + 3 * K] = l;
}
__global__ void splitBT_k(const float* __restrict__ src, bf16* __restrict__ dst) {
    int idx = blockIdx.x * 256 + threadIdx.x;    // 512*512
    int n = idx >> 9, k = idx & 511;
    float v = src[(long)k * Nst + n];
    bf16 h = __float2bfloat16(v);
    bf16 l = __float2bfloat16(v - __bfloat162float(h));
    long o = (long)n * KS4 + k;
    dst[o] = h; dst[o + 512] = h; dst[o + 1024] = l; dst[o + 1536] = l;
}
__global__ void splitN_k() {                     // all 20 natural B-form splits
    long idx = (long)blockIdx.x * 256 + threadIdx.x;   // 20*512*512
    int slot = (int)(idx >> 18);
    int rem  = (int)(idx & 262143);
    int n = rem >> 9, k = rem & 511;
    float v = g_pw[slot][n * 512 + k];
    bf16 h = __float2bfloat16(v);
    bf16 l = __float2bfloat16(v - __bfloat162float(h));
    bf16* d = g_pwN[slot] + (long)n * KS4 + k;
    d[0] = h; d[512] = h; d[1024] = l; d[1536] = l;
}
__global__ void bGrev_k() {
    int idx = blockIdx.x * 256 + threadIdx.x;    // 512*128
    int n = idx >> 7, i = idx & 127;
    float v = g_G[(long)(127 - i) * Nst + n];
    bf16 h = __float2bfloat16(v);
    bf16 l = __float2bfloat16(v - __bfloat162float(h));
    long o = (long)n * UK4 + i;
    g_GrevB[o] = h; g_GrevB[o + 128] = h; g_GrevB[o + 256] = l; g_GrevB[o + 384] = l;
}
__global__ void gmatB_k() {
    long idx = (long)blockIdx.x * 256 + threadIdx.x;  // 65536*128
    int i = (int)(idx & 127);
    long rr = idx >> 7;                               // g = j*512+n
    int j = (int)(rr >> 9), n = (int)(rr & 511);
    float v = (j >= i) ? g_G[(long)(j - i) * Nst + n] : 0.f;
    bf16 h = __float2bfloat16(v);
    bf16 l = __float2bfloat16(v - __bfloat162float(h));
    long o = rr * UK4 + i;
    g_GmatB[o] = h; g_GmatB[o + 128] = h; g_GmatB[o + 256] = l; g_GmatB[o + 384] = l;
}
__global__ void gvec_k(const float* __restrict__ b) {
    __shared__ float bs[Nst];
    int t = threadIdx.x;
    for (int i = t; i < Nst; i += 256) bs[i] = b[i];
    __syncthreads();
    int idx = blockIdx.x * 256 + t;
    int j = idx >> 9, n = idx & 511;
    const float* row = g_pw[j] + (long)n * Nst;
    float s = 0.f;
#pragma unroll 8
    for (int k = 0; k < Nst; k++) s += row[k] * bs[k];
    g_G[(long)(j + 1) * Nst + n] = s;
}

// ---------------- host ----------------
#define SMEM_S ((128 + 128) * LDA * 3 * 2)     // 110592 B
#define SMEM_B ((256 + 128) * LDA * 3 * 2)     // 165888 B

static void TG(int cfg,
               const bf16* A, long aB, long aZ,
               const bf16* Bp, long bB, long bZ,
               float* Cp, long cB, long cRS, long cZ,
               const float* Dp, long dB, long dRS, int dM,
               bf16* SAp, long saB, long saZ,
               bf16* SBp, long sbB, long sbZ,
               int M, int Nn, int Ks, int nz)
{
    if (cfg == 0) {
        dim3 g(Nn / 128, (M + 127) / 128, nz);
        tgemm_k<128><<<g, 256, SMEM_S>>>(A, aB, aZ, Bp, bB, bZ, Cp, cB, cRS, cZ,
                                         Dp, dB, dRS, dM, SAp, saB, saZ, SBp, sbB, sbZ, M, Ks);
    } else {
        dim3 g(Nn / 128, (M + 255) / 256, nz);
        tgemm_k<256><<<g, 256, SMEM_B>>>(A, aB, aZ, Bp, bB, bZ, Cp, cB, cRS, cZ,
                                         Dp, dB, dRS, dM, SAp, saB, saZ, SBp, sbB, sbZ, M, Ks);
    }
}

extern "C" void kernel_launch(void* const* d_in, const int* in_sizes, int n_in,
                              void* d_out, int out_size)
{
    const float* u  = (const float*)d_in[0];
    const float* Ab = (const float*)d_in[1];
    const float* Bb = (const float*)d_in[2];
    const float* x0 = (const float*)d_in[3];
    float* out = (float*)d_out;

    cudaFuncSetAttribute(tgemm_k<128>, cudaFuncAttributeMaxDynamicSharedMemorySize, SMEM_S);
    cudaFuncSetAttribute(tgemm_k<256>, cudaFuncAttributeMaxDynamicSharedMemorySize, SMEM_B);

    float *pw, *G, *R0, *R1, *OutA;
    bf16 *pwA, *pwB, *pwN, *GA, *GrevB, *UA, *GmatB, *R0e, *R1e, *OutAe;
    cudaGetSymbolAddress((void**)&pw,    g_pw);
    cudaGetSymbolAddress((void**)&pwA,   g_pwA);
    cudaGetSymbolAddress((void**)&pwB,   g_pwB);
    cudaGetSymbolAddress((void**)&pwN,   g_pwN);
    cudaGetSymbolAddress((void**)&G,     g_G);
    cudaGetSymbolAddress((void**)&GA,    g_GA);
    cudaGetSymbolAddress((void**)&GrevB, g_GrevB);
    cudaGetSymbolAddress((void**)&UA,    g_UA);
    cudaGetSymbolAddress((void**)&GmatB, g_GmatB);
    cudaGetSymbolAddress((void**)&R0,    g_R0);
    cudaGetSymbolAddress((void**)&R1,    g_R1);
    cudaGetSymbolAddress((void**)&R0e,   g_R0e);
    cudaGetSymbolAddress((void**)&R1e,   g_R1e);
    cudaGetSymbolAddress((void**)&OutA,  g_OutA);
    cudaGetSymbolAddress((void**)&OutAe, g_OutAe);

    auto PWf = [&](int s) { return pw  + (long)s * NN; };
    auto PA  = [&](int s) { return pwA + (long)s * SLOT4; };
    auto PB  = [&](int s) { return pwB + (long)s * SLOT4; };
    auto PN  = [&](int s) { return pwN + (long)s * SLOT4; };

    // ---- input splits ----
    splitA_k<<<(512 * 512) / 256, 256>>>(Ab, 512, PA(0), 512, 512);
    splitBT_k<<<(512 * 512) / 256, 256>>>(Ab, PB(0));
    cudaMemcpyAsync(PWf(0), Ab, NN * sizeof(float), cudaMemcpyDeviceToDevice);
    splitA_k<<<(512 * 128) / 256, 256>>>(u, 128, UA, 512, 128);
    splitA_k<<<2, 256>>>(x0, 512, R0e, 1, 512);
    cudaMemcpyAsync(R0, x0, Nst * sizeof(float), cudaMemcpyDeviceToDevice);

    // ---- power chain: slots 0..7 = A^1..A^8; 8..10 = A^16/32/64; 11..19 = A^(128*2^k)
    TG(0, PA(0), 0, 0, PB(0), 0, 0, PWf(1), 0, 512, 0,
       nullptr, 0, 0, 0, PA(1), 0, 0, PB(1), 0, 0, 512, 512, KS4, 1);          // A^2
    TG(0, PA(0), 0, SLOT4, PB(1), 0, 0, PWf(2), 0, 512, NN,
       nullptr, 0, 0, 0, PA(2), 0, SLOT4, PB(2), 0, SLOT4, 512, 512, KS4, 2);  // A^3,A^4
    TG(0, PA(0), 0, SLOT4, PB(3), 0, 0, PWf(4), 0, 512, NN,
       nullptr, 0, 0, 0, PA(4), 0, SLOT4, PB(4), 0, SLOT4, 512, 512, KS4, 4);  // A^5..A^8
    for (int s = 8; s <= 19; s++)
        TG(0, PA(s - 1), 0, 0, PB(s - 1), 0, 0, PWf(s), 0, 512, 0,
           nullptr, 0, 0, 0, PA(s), 0, 0, PB(s), 0, 0, 512, 512, KS4, 1);

    // natural B-form splits of all powers (for every x @ P^T GEMM below)
    splitN_k<<<20480, 256>>>();

    // ---- conv kernel G[0..127] ----
    cudaMemcpyAsync(G, Bb, Nst * sizeof(float), cudaMemcpyDeviceToDevice);
    gvec_k<<<16, 256>>>(Bb);                                   // G[1..8] fp32 matvecs
    splitA_k<<<(8 * 512) / 256, 256>>>(G, 512, GA, 8, 512);
    for (int t = 3; t <= 6; t++) {
        int sI = 1 << t;                                       // 8,16,32,64
        TG(0, GA, 0, 0, PN(4 + t), 0, 0, G, (long)sI * 512, 512, 0,
           nullptr, 0, 0, 0,
           (t < 6) ? GA : nullptr, (long)sI * KS4, 0, nullptr, 0, 0,
           sI, 512, KS4, 1);
    }
    bGrev_k<<<(512 * 128) / 256, 256>>>();
    gmatB_k<<<32768, 256>>>();

    // ---- driving terms rows 1..511 ----
    TG(0, UA, 0, 0, GrevB, 0, 0, R0, 512, 512, 0,
       nullptr, 0, 0, 0, R0e, KS4, 0, nullptr, 0, 0, 511, 512, UK4, 1);

    // ---- log-doubling scan (9 levels) ----
    float* cur = R0;  float* nxt = R1;
    bf16*  curE = R0e; bf16* nxtE = R1e;
    for (int k = 0; k < 9; k++) {
        int h = 1 << k;
        cudaMemcpyAsync(nxt, cur, (size_t)h * Nst * sizeof(float),
                        cudaMemcpyDeviceToDevice);
        cudaMemcpyAsync(nxtE, curE, (size_t)h * KS4 * sizeof(bf16),
                        cudaMemcpyDeviceToDevice);
        TG(0, curE, 0, 0, PN(11 + k), 0, 0, nxt, (long)h * 512, 512, 0,
           cur, (long)h * 512, 512, 1,
           nxtE, (long)h * KS4, 0, nullptr, 0, 0,
           512 - h, 512, KS4, 1);
        float* tf = cur; cur = nxt; nxt = tf;
        bf16*  tb = curE; curE = nxtE; nxtE = tb;
    }

    // ---- Part A stage 1: rows j=0..7 via one z=8 batched GEMM ----
    TG(0, curE, 0, 0, pwN, 0, SLOT4, OutA, 0, 512, (long)Cc * 512,
       nullptr, 0, 0, 0, OutAe, 0, (long)Cc * KS4, nullptr, 0, 0,
       512, 512, KS4, 8);

    // ---- Part A stage 2: log-doubling over j-blocks (R=8,16,32,64) ----
    for (int s = 0; s < 4; s++) {
        int R = 8 << s;                       // B = A^R -> slots 7,8,9,10
        TG(1, OutAe, 0, 0, PN(7 + s), 0, 0, OutA, (long)R * Cc * 512, 512, 0,
           nullptr, 0, 0, 0,
           (s < 3) ? OutAe : nullptr, (long)R * Cc * KS4, 0, nullptr, 0, 0,
           R * Cc, 512, KS4, 1);
    }

    // ---- Part B: causal conv + Part A combine, directly into d_out ----
    TG(1, UA, 0, 0, GmatB, 0, 0, out, 0, 65536, 0,
       OutA, 0, 0, 2,
       nullptr, 0, 0, nullptr, 0, 0,
       512, 65536, UK4, 1);

    (void)in_sizes; (void)n_in; (void)out_size;
}

// round 16
// speedup vs baseline: 1.6810x; 1.6810x over previous
#include <cuda_runtime.h>
#include <cuda_bf16.h>
#include <cstdint>

#define Nst 512
#define Cc  512
#define NN  ((long)Nst * Nst)
#define KS4 2048                         // 4-segment K' for K=512 (row stride)
#define KS3 1536                         // 3-segment K' (prefix of same buffer)
#define UK4 512                          // 4-segment K' for K=128
#define UK3 384
#define SLOT4 ((long)Nst * KS4)
#define KC   64
#define LDA  72                          // KC + 8 bf16 pad

typedef __nv_bfloat16 bf16;

// ---------------- static scratch (no runtime allocation) ----------------
__device__ float g_pw[20][Nst * Nst];        // fp32 powers
__device__ bf16  g_pwA[20][Nst * KS4];       // A-form split [h|l|h|l], natural rows
__device__ bf16  g_pwB[20][Nst * KS4];       // B-form split [h|h|l|l], TRANSPOSED (squaring)
__device__ bf16  g_pwN[20][Nst * KS4];       // B-form split [h|h|l|l], natural rows (x@P^T)
__device__ float g_G[128 * Nst];             // G[m] = A^m b
__device__ bf16  g_GA[64 * KS4];             // A-form split of G rows
__device__ bf16  g_GrevB[Nst * UK4];         // B-form of reversed G (K=128)
__device__ bf16  g_UA[Cc * UK4];             // A-form of u chunks (K=128)
__device__ bf16  g_GmatB[(size_t)65536 * UK4];
__device__ float g_R0[Cc * Nst], g_R1[Cc * Nst];
__device__ bf16  g_R0e[Cc * KS4], g_R1e[Cc * KS4];
__device__ float g_OutA[(size_t)128 * Cc * Nst];   // [j][c][n]
__device__ bf16  g_OutAe[(size_t)64 * Cc * KS4];   // A-form of rows j=0..63

// ---------------- helpers ----------------
__device__ __forceinline__ uint32_t s2u(const void* p) {
    uint32_t a;
    asm("{ .reg .u64 t; cvta.to.shared.u64 t, %1; cvt.u32.u64 %0, t; }" : "=r"(a) : "l"(p));
    return a;
}
__device__ __forceinline__ void cpasync(uint32_t d, const void* g, int srcsz) {
    asm volatile("cp.async.ca.shared.global [%0], [%1], 16, %2;"
                 :: "r"(d), "l"(g), "r"(srcsz) : "memory");
}
__device__ __forceinline__ void cpcommit() {
    asm volatile("cp.async.commit_group;" ::: "memory");
}
template<int n> __device__ __forceinline__ void cpwait() {
    asm volatile("cp.async.wait_group %0;" :: "n"(n) : "memory");
}
__device__ __forceinline__ void ldsm4(uint32_t &r0, uint32_t &r1, uint32_t &r2, uint32_t &r3, uint32_t a) {
    asm volatile("ldmatrix.sync.aligned.m8n8.x4.shared.b16 {%0,%1,%2,%3}, [%4];"
                 : "=r"(r0), "=r"(r1), "=r"(r2), "=r"(r3) : "r"(a));
}
__device__ __forceinline__ void mma16816(float* c, const uint32_t* a, const uint32_t* b) {
    asm volatile("mma.sync.aligned.m16n8k16.row.col.f32.bf16.bf16.f32 "
                 "{%0,%1,%2,%3}, {%4,%5,%6,%7}, {%8,%9}, {%0,%1,%2,%3};"
                 : "+f"(c[0]), "+f"(c[1]), "+f"(c[2]), "+f"(c[3])
                 : "r"(a[0]), "r"(a[1]), "r"(a[2]), "r"(a[3]), "r"(b[0]), "r"(b[1]));
}

// ============================================================================
// bf16 tensor-core GEMM: C[m,g] = sum_{k<Ks} A[m,k]*B[g,k] (+Dadd), M-guarded.
// Row strides aLD/bLD decoupled from Ks so the same 4-seg buffers serve
// 3-term (Ks=3K) and 4-term (Ks=4K) products.
// Tiles: <64,64> (serial small GEMMs), <128,128>, <256,128>. 8 warps (4m x 2n).
// 3-stage cp.async pipeline, one __syncthreads per K-stage.
// ============================================================================
template<int BM, int BN>
__global__ void __launch_bounds__(256, 1)
tgemm_k(const bf16* __restrict__ A, long aBase, long aZS, int aLD,
        const bf16* __restrict__ B, long bBase, long bZS, int bLD,
        float* __restrict__ C, long cBase, long cRS, long cZS,
        const float* __restrict__ Dadd, long dBase, long dRS, int dMode,
        bf16* __restrict__ SA, long saBase, long saZS,
        bf16* __restrict__ SB, long sbBase, long sbZS,
        int M, int Ks)
{
    constexpr int WM = BM / 4, WN = BN / 2;
    constexpr int MI = WM / 16, NI = WN / 8;
    constexpr int ROWS = BM + BN;
    constexpr int STAGE = ROWS * LDA;
    extern __shared__ bf16 sm[];

    int tid = threadIdx.x;
    int lane = tid & 31, wid = tid >> 5;
    int bm = blockIdx.y * BM, bn = blockIdx.x * BN;
    int z = blockIdx.z;
    const bf16* Ap = A + aBase + (long)z * aZS;
    const bf16* Bp = B + bBase + (long)z * bZS;
    int wm = (wid & 3) * WM;
    int wn = (wid >> 2) * WN;

    float acc[MI][NI][4];
#pragma unroll
    for (int i = 0; i < MI; i++)
#pragma unroll
        for (int j = 0; j < NI; j++)
#pragma unroll
            for (int p = 0; p < 4; p++) acc[i][j][p] = 0.f;

    int nc = Ks / KC;

    auto ldg = [&](int s) {
        bf16* st = sm + (s % 3) * STAGE;
        int kc = s * KC;
#pragma unroll
        for (int t = 0; t < ROWS / 32; t++) {
            int id = tid + t * 256;
            int r = id >> 3, c = (id & 7) << 3;
            const bf16* src;
            int sz = 16;
            if (r < BM) {
                int gr = bm + r;
                int grs = gr < M ? gr : 0;
                src = Ap + (long)grs * aLD + kc + c;
                sz = gr < M ? 16 : 0;
            } else {
                src = Bp + (long)(bn + r - BM) * bLD + kc + c;
            }
            cpasync(s2u(st + r * LDA + c), src, sz);
        }
    };

    auto comp = [&](int s) {
        const bf16* as = sm + (s % 3) * STAGE;
        const bf16* bs = as + BM * LDA;
        int lr = lane & 15, lk = (lane >> 4) << 3;
#pragma unroll
        for (int ks = 0; ks < KC / 16; ks++) {
            uint32_t af[MI][4], bfr[NI][2];
#pragma unroll
            for (int mi = 0; mi < MI; mi++) {
                uint32_t a = s2u(as + (wm + mi * 16 + lr) * LDA + ks * 16 + lk);
                ldsm4(af[mi][0], af[mi][1], af[mi][2], af[mi][3], a);
            }
#pragma unroll
            for (int nj = 0; nj < NI / 2; nj++) {
                uint32_t r0, r1, r2, r3;
                uint32_t a = s2u(bs + (wn + nj * 16 + lr) * LDA + ks * 16 + lk);
                ldsm4(r0, r1, r2, r3, a);
                bfr[nj * 2][0] = r0;     bfr[nj * 2][1] = r2;
                bfr[nj * 2 + 1][0] = r1; bfr[nj * 2 + 1][1] = r3;
            }
#pragma unroll
            for (int mi = 0; mi < MI; mi++)
#pragma unroll
                for (int ni = 0; ni < NI; ni++)
                    mma16816(acc[mi][ni], af[mi], bfr[ni]);
        }
    };

    ldg(0); cpcommit();
    if (nc > 1) { ldg(1); cpcommit(); }
    for (int s = 0; s < nc; s++) {
        if (s + 1 < nc) cpwait<1>(); else cpwait<0>();
        __syncthreads();
        comp(s);
        if (s + 2 < nc) { ldg(s + 2); cpcommit(); }
    }

    // ---- epilogue ----
    int group = lane >> 2, t4 = lane & 3;
#pragma unroll
    for (int mi = 0; mi < MI; mi++) {
#pragma unroll
        for (int rh = 0; rh < 2; rh++) {
            int m = bm + wm + mi * 16 + rh * 8 + group;
            if (m >= M) continue;
            long cro = cBase + (long)z * cZS + (long)m * cRS;
#pragma unroll
            for (int ni = 0; ni < NI; ni++) {
                int n = bn + wn + ni * 8 + t4 * 2;
                float v0 = acc[mi][ni][rh * 2 + 0];
                float v1 = acc[mi][ni][rh * 2 + 1];
                if (dMode == 1) {
                    const float* dp = Dadd + dBase + (long)m * dRS + n;
                    v0 += dp[0]; v1 += dp[1];
                } else if (dMode == 2) {
                    long db = ((long)(n >> 9) << 18) + ((long)m << 9) + (n & 511);
                    v0 += Dadd[db]; v1 += Dadd[db + 1];
                }
                float2 vv; vv.x = v0; vv.y = v1;
                *(float2*)&C[cro + n] = vv;
                if (SA) {
                    bf16 h0 = __float2bfloat16(v0);
                    bf16 l0 = __float2bfloat16(v0 - __bfloat162float(h0));
                    bf16 h1 = __float2bfloat16(v1);
                    bf16 l1 = __float2bfloat16(v1 - __bfloat162float(h1));
                    long so = saBase + (long)z * saZS + (long)m * KS4 + n;
                    SA[so] = h0;        SA[so + 512] = l0;
                    SA[so + 1024] = h0; SA[so + 1536] = l0;
                    SA[so + 1] = h1;    SA[so + 513] = l1;
                    SA[so + 1025] = h1; SA[so + 1537] = l1;
                }
                if (SB) {
                    bf16 h0 = __float2bfloat16(v0);
                    bf16 l0 = __float2bfloat16(v0 - __bfloat162float(h0));
                    bf16 h1 = __float2bfloat16(v1);
                    bf16 l1 = __float2bfloat16(v1 - __bfloat162float(h1));
                    long so0 = sbBase + (long)z * sbZS + (long)n * KS4 + m;
                    SB[so0] = h0; SB[so0 + 512] = h0;
                    SB[so0 + 1024] = l0; SB[so0 + 1536] = l0;
                    long so1 = so0 + KS4;
                    SB[so1] = h1; SB[so1 + 512] = h1;
                    SB[so1 + 1024] = l1; SB[so1 + 1536] = l1;
                }
            }
        }
    }
}

// ---------------- conversion kernels (4-segment layouts) ----------------
__global__ void splitA_k(const float* __restrict__ src, int ld,
                         bf16* __restrict__ dst, int M, int K) {
    long idx = (long)blockIdx.x * 256 + threadIdx.x;
    if (idx >= (long)M * K) return;
    int mm = (int)(idx / K), k = (int)(idx - (long)mm * K);
    float v = src[(long)mm * ld + k];
    bf16 h = __float2bfloat16(v);
    bf16 l = __float2bfloat16(v - __bfloat162float(h));
    long o = (long)mm * 4 * K + k;
    dst[o] = h; dst[o + K] = l; dst[o + 2 * K] = h; dst[o + 3 * K] = l;
}
__global__ void splitBT_k(const float* __restrict__ src, bf16* __restrict__ dst) {
    int idx = blockIdx.x * 256 + threadIdx.x;    // 512*512
    int n = idx >> 9, k = idx & 511;
    float v = src[(long)k * Nst + n];
    bf16 h = __float2bfloat16(v);
    bf16 l = __float2bfloat16(v - __bfloat162float(h));
    long o = (long)n * KS4 + k;
    dst[o] = h; dst[o + 512] = h; dst[o + 1024] = l; dst[o + 1536] = l;
}
__global__ void splitN_k() {                     // all 20 natural B-form splits
    long idx = (long)blockIdx.x * 256 + threadIdx.x;   // 20*512*512
    int slot = (int)(idx >> 18);
    int rem  = (int)(idx & 262143);
    int n = rem >> 9, k = rem & 511;
    float v = g_pw[slot][n * 512 + k];
    bf16 h = __float2bfloat16(v);
    bf16 l = __float2bfloat16(v - __bfloat162float(h));
    bf16* d = g_pwN[slot] + (long)n * KS4 + k;
    d[0] = h; d[512] = h; d[1024] = l; d[1536] = l;
}
__global__ void bGrev_k() {
    int idx = blockIdx.x * 256 + threadIdx.x;    // 512*128
    int n = idx >> 7, i = idx & 127;
    float v = g_G[(long)(127 - i) * Nst + n];
    bf16 h = __float2bfloat16(v);
    bf16 l = __float2bfloat16(v - __bfloat162float(h));
    long o = (long)n * UK4 + i;
    g_GrevB[o] = h; g_GrevB[o + 128] = h; g_GrevB[o + 256] = l; g_GrevB[o + 384] = l;
}
__global__ void gmatB_k() {
    long idx = (long)blockIdx.x * 256 + threadIdx.x;  // 65536*128
    int i = (int)(idx & 127);
    long rr = idx >> 7;                               // g = j*512+n
    int j = (int)(rr >> 9), n = (int)(rr & 511);
    float v = (j >= i) ? g_G[(long)(j - i) * Nst + n] : 0.f;
    bf16 h = __float2bfloat16(v);
    bf16 l = __float2bfloat16(v - __bfloat162float(h));
    long o = rr * UK4 + i;
    g_GmatB[o] = h; g_GmatB[o + 128] = h; g_GmatB[o + 256] = l; g_GmatB[o + 384] = l;
}
__global__ void gvec_k(const float* __restrict__ b) {
    __shared__ float bs[Nst];
    int t = threadIdx.x;
    for (int i = t; i < Nst; i += 256) bs[i] = b[i];
    __syncthreads();
    int idx = blockIdx.x * 256 + t;
    int j = idx >> 9, n = idx & 511;
    const float* row = g_pw[j] + (long)n * Nst;
    float s = 0.f;
#pragma unroll 8
    for (int k = 0; k < Nst; k++) s += row[k] * bs[k];
    g_G[(long)(j + 1) * Nst + n] = s;
}

// ---------------- host ----------------
#define SMEM_T ((64 + 64)  * LDA * 3 * 2)      //  55296 B
#define SMEM_S ((128 + 128) * LDA * 3 * 2)     // 110592 B
#define SMEM_B ((256 + 128) * LDA * 3 * 2)     // 165888 B

static void TG(int cfg,
               const bf16* A, long aB, long aZ, int aLD,
               const bf16* Bp, long bB, long bZ, int bLD,
               float* Cp, long cB, long cRS, long cZ,
               const float* Dp, long dB, long dRS, int dM,
               bf16* SAp, long saB, long saZ,
               bf16* SBp, long sbB, long sbZ,
               int M, int Nn, int Ks, int nz)
{
    if (cfg == 0) {
        dim3 g(Nn / 64, (M + 63) / 64, nz);
        tgemm_k<64, 64><<<g, 256, SMEM_T>>>(A, aB, aZ, aLD, Bp, bB, bZ, bLD,
            Cp, cB, cRS, cZ, Dp, dB, dRS, dM, SAp, saB, saZ, SBp, sbB, sbZ, M, Ks);
    } else if (cfg == 1) {
        dim3 g(Nn / 128, (M + 127) / 128, nz);
        tgemm_k<128, 128><<<g, 256, SMEM_S>>>(A, aB, aZ, aLD, Bp, bB, bZ, bLD,
            Cp, cB, cRS, cZ, Dp, dB, dRS, dM, SAp, saB, saZ, SBp, sbB, sbZ, M, Ks);
    } else {
        dim3 g(Nn / 128, (M + 255) / 256, nz);
        tgemm_k<256, 128><<<g, 256, SMEM_B>>>(A, aB, aZ, aLD, Bp, bB, bZ, bLD,
            Cp, cB, cRS, cZ, Dp, dB, dRS, dM, SAp, saB, saZ, SBp, sbB, sbZ, M, Ks);
    }
}

extern "C" void kernel_launch(void* const* d_in, const int* in_sizes, int n_in,
                              void* d_out, int out_size)
{
    const float* u  = (const float*)d_in[0];
    const float* Ab = (const float*)d_in[1];
    const float* Bb = (const float*)d_in[2];
    const float* x0 = (const float*)d_in[3];
    float* out = (float*)d_out;

    cudaFuncSetAttribute((const void*)tgemm_k<64, 64>,   cudaFuncAttributeMaxDynamicSharedMemorySize, SMEM_T);
    cudaFuncSetAttribute((const void*)tgemm_k<128, 128>, cudaFuncAttributeMaxDynamicSharedMemorySize, SMEM_S);
    cudaFuncSetAttribute((const void*)tgemm_k<256, 128>, cudaFuncAttributeMaxDynamicSharedMemorySize, SMEM_B);

    float *pw, *G, *R0, *R1, *OutA;
    bf16 *pwA, *pwB, *pwN, *GA, *GrevB, *UA, *GmatB, *R0e, *R1e, *OutAe;
    cudaGetSymbolAddress((void**)&pw,    g_pw);
    cudaGetSymbolAddress((void**)&pwA,   g_pwA);
    cudaGetSymbolAddress((void**)&pwB,   g_pwB);
    cudaGetSymbolAddress((void**)&pwN,   g_pwN);
    cudaGetSymbolAddress((void**)&G,     g_G);
    cudaGetSymbolAddress((void**)&GA,    g_GA);
    cudaGetSymbolAddress((void**)&GrevB, g_GrevB);
    cudaGetSymbolAddress((void**)&UA,    g_UA);
    cudaGetSymbolAddress((void**)&GmatB, g_GmatB);
    cudaGetSymbolAddress((void**)&R0,    g_R0);
    cudaGetSymbolAddress((void**)&R1,    g_R1);
    cudaGetSymbolAddress((void**)&R0e,   g_R0e);
    cudaGetSymbolAddress((void**)&R1e,   g_R1e);
    cudaGetSymbolAddress((void**)&OutA,  g_OutA);
    cudaGetSymbolAddress((void**)&OutAe, g_OutAe);

    auto PWf = [&](int s) { return pw  + (long)s * NN; };
    auto PA  = [&](int s) { return pwA + (long)s * SLOT4; };
    auto PB  = [&](int s) { return pwB + (long)s * SLOT4; };
    auto PN  = [&](int s) { return pwN + (long)s * SLOT4; };

    // ---- input splits ----
    splitA_k<<<(512 * 512) / 256, 256>>>(Ab, 512, PA(0), 512, 512);
    splitBT_k<<<(512 * 512) / 256, 256>>>(Ab, PB(0));
    cudaMemcpyAsync(PWf(0), Ab, NN * sizeof(float), cudaMemcpyDeviceToDevice);
    splitA_k<<<(512 * 128) / 256, 256>>>(u, 128, UA, 512, 128);
    splitA_k<<<2, 256>>>(x0, 512, R0e, 1, 512);
    cudaMemcpyAsync(R0, x0, Nst * sizeof(float), cudaMemcpyDeviceToDevice);

    // ---- power chain (4-term, 64x64 tiles): slots 0..7 = A^1..A^8;
    //      8..10 = A^16/32/64; 11..19 = A^(128*2^k)
    TG(0, PA(0), 0, 0, KS4, PB(0), 0, 0, KS4, PWf(1), 0, 512, 0,
       nullptr, 0, 0, 0, PA(1), 0, 0, PB(1), 0, 0, 512, 512, KS4, 1);              // A^2
    TG(0, PA(0), 0, SLOT4, KS4, PB(1), 0, 0, KS4, PWf(2), 0, 512, NN,
       nullptr, 0, 0, 0, PA(2), 0, SLOT4, PB(2), 0, SLOT4, 512, 512, KS4, 2);      // A^3,A^4
    TG(0, PA(0), 0, SLOT4, KS4, PB(3), 0, 0, KS4, PWf(4), 0, 512, NN,
       nullptr, 0, 0, 0, PA(4), 0, SLOT4, PB(4), 0, SLOT4, 512, 512, KS4, 4);      // A^5..A^8
    for (int s = 8; s <= 19; s++)
        TG(0, PA(s - 1), 0, 0, KS4, PB(s - 1), 0, 0, KS4, PWf(s), 0, 512, 0,
           nullptr, 0, 0, 0, PA(s), 0, 0, PB(s), 0, 0, 512, 512, KS4, 1);

    // natural B-form splits of all powers
    splitN_k<<<20480, 256>>>();

    // ---- conv kernel G[0..127] (4-term) ----
    cudaMemcpyAsync(G, Bb, Nst * sizeof(float), cudaMemcpyDeviceToDevice);
    gvec_k<<<16, 256>>>(Bb);
    splitA_k<<<(8 * 512) / 256, 256>>>(G, 512, GA, 8, 512);
    for (int t = 3; t <= 6; t++) {
        int sI = 1 << t;                                       // 8,16,32,64
        TG(0, GA, 0, 0, KS4, PN(4 + t), 0, 0, KS4, G, (long)sI * 512, 512, 0,
           nullptr, 0, 0, 0,
           (t < 6) ? GA : nullptr, (long)sI * KS4, 0, nullptr, 0, 0,
           sI, 512, KS4, 1);
    }
    bGrev_k<<<(512 * 128) / 256, 256>>>();
    gmatB_k<<<32768, 256>>>();

    // ---- driving terms rows 1..511 (4-term, K=128 -> Ks=512) ----
    TG(0, UA, 0, 0, UK4, GrevB, 0, 0, UK4, R0, 512, 512, 0,
       nullptr, 0, 0, 0, R0e, KS4, 0, nullptr, 0, 0, 511, 512, UK4, 1);

    // ---- log-doubling scan (9 levels, 4-term, 64x64 tiles) ----
    float* cur = R0;  float* nxt = R1;
    bf16*  curE = R0e; bf16* nxtE = R1e;
    for (int k = 0; k < 9; k++) {
        int h = 1 << k;
        cudaMemcpyAsync(nxt, cur, (size_t)h * Nst * sizeof(float),
                        cudaMemcpyDeviceToDevice);
        cudaMemcpyAsync(nxtE, curE, (size_t)h * KS4 * sizeof(bf16),
                        cudaMemcpyDeviceToDevice);
        TG(0, curE, 0, 0, KS4, PN(11 + k), 0, 0, KS4, nxt, (long)h * 512, 512, 0,
           cur, (long)h * 512, 512, 1,
           nxtE, (long)h * KS4, 0, nullptr, 0, 0,
           512 - h, 512, KS4, 1);
        float* tf = cur; cur = nxt; nxt = tf;
        bf16*  tb = curE; curE = nxtE; nxtE = tb;
    }

    // ---- Part A stage 1 (3-term): rows j=0..7 via one z=8 batched GEMM ----
    TG(1, curE, 0, 0, KS4, pwN, 0, SLOT4, KS4, OutA, 0, 512, (long)Cc * 512,
       nullptr, 0, 0, 0, OutAe, 0, (long)Cc * KS4, nullptr, 0, 0,
       512, 512, KS3, 8);

    // ---- Part A stage 2 (3-term): log-doubling over j-blocks (R=8,16,32,64) ----
    for (int s = 0; s < 4; s++) {
        int R = 8 << s;                       // B = A^R -> slots 7,8,9,10
        TG(2, OutAe, 0, 0, KS4, PN(7 + s), 0, 0, KS4, OutA, (long)R * Cc * 512, 512, 0,
           nullptr, 0, 0, 0,
           (s < 3) ? OutAe : nullptr, (long)R * Cc * KS4, 0, nullptr, 0, 0,
           R * Cc, 512, KS3, 1);
    }

    // ---- Part B (3-term): causal conv + Part A combine, directly into d_out ----
    TG(2, UA, 0, 0, UK4, GmatB, 0, 0, UK4, out, 0, 65536, 0,
       OutA, 0, 0, 2,
       nullptr, 0, 0, nullptr, 0, 0,
       512, 65536, UK3, 1);

    (void)in_sizes; (void)n_in; (void)out_size;
}